// round 4
// baseline (speedup 1.0000x reference)
#include <cuda_runtime.h>

#define NN 50000
#define NE 800000
#define SCAN_B 512
#define SCAN_NB ((NN + SCAN_B - 1) / SCAN_B)  // 98

// ---------------------------------------------------------------------------
// Scratch (__device__ globals; float4-typed where vector-accessed)
// ---------------------------------------------------------------------------
__device__ int    g_is64;            // edge_index dtype flag (detected on device)
__device__ float  g_deg[NN];
__device__ float  g_dinv[NN];
__device__ int    g_cnt[NN];
__device__ int    g_off[NN + 1];
__device__ int    g_cursor[NN];
__device__ int    g_bsum[SCAN_NB];
__device__ int    g_bpre[SCAN_NB];
__device__ int    g_src[NE];         // edge sources, sorted by destination
__device__ float  g_coef[NE];        // dinv[row]*w*dinv[col], same order
__device__ float4 g_h4[NN * 32];     // layer activations [NN][128]
__device__ float4 g_m4[NN * 32];     // GEMM output       [NN][128]

// ---------------------------------------------------------------------------
// Edge-index dtype detection: if data is int64 (ids < 2^31), every odd int32
// word within the first 1.6M int32s is a zero high-word. If int32, odd words
// are random node ids — P(2048 samples all zero) ~ (2e-5)^2048 = 0.
// ---------------------------------------------------------------------------
__global__ void k_detect(const int* __restrict__ ei32) {
    __shared__ int nz;
    if (threadIdx.x == 0) nz = 0;
    __syncthreads();
    for (int i = threadIdx.x; i < 2048; i += blockDim.x)
        if (ei32[2 * i + 1] != 0) nz = 1;
    __syncthreads();
    if (threadIdx.x == 0) g_is64 = (nz == 0) ? 1 : 0;
}

__device__ __forceinline__ int load_idx(const void* ei, long i) {
    int v = g_is64 ? (int)((const long long*)ei)[i] : ((const int*)ei)[i];
    return min(max(v, 0), NN - 1);  // defensive clamp: wrong-answer beats trap
}

// ---------------------------------------------------------------------------
// Normalization + CSR build
// ---------------------------------------------------------------------------
__global__ void k_zero() {
    int i = blockIdx.x * blockDim.x + threadIdx.x;
    if (i < NN) { g_deg[i] = 0.0f; g_cnt[i] = 0; }
}

__global__ void k_deg_count(const void* __restrict__ ei, const float* __restrict__ ew) {
    int e = blockIdx.x * blockDim.x + threadIdx.x;
    if (e < NE) {
        int col = load_idx(ei, (long)NE + e);
        atomicAdd(&g_deg[col], ew[e]);
        atomicAdd(&g_cnt[col], 1);
    }
}

__global__ void k_dinv() {
    int i = blockIdx.x * blockDim.x + threadIdx.x;
    // self-loop adds weight 1 -> deg >= 1 always
    if (i < NN) g_dinv[i] = rsqrtf(g_deg[i] + 1.0f);
}

__global__ void k_scan1() {
    __shared__ int s[SCAN_B];
    int tid = threadIdx.x;
    int i = blockIdx.x * SCAN_B + tid;
    int v = (i < NN) ? g_cnt[i] : 0;
    s[tid] = v;
    __syncthreads();
#pragma unroll
    for (int off = 1; off < SCAN_B; off <<= 1) {
        int t = (tid >= off) ? s[tid - off] : 0;
        __syncthreads();
        s[tid] += t;
        __syncthreads();
    }
    if (i < NN) g_off[i] = s[tid] - v;  // exclusive
    if (tid == SCAN_B - 1) g_bsum[blockIdx.x] = s[tid];
}

__global__ void k_scan2() {
    if (threadIdx.x == 0) {
        int acc = 0;
        for (int b = 0; b < SCAN_NB; b++) { g_bpre[b] = acc; acc += g_bsum[b]; }
    }
}

__global__ void k_scan3() {
    int i = blockIdx.x * blockDim.x + threadIdx.x;
    if (i < NN) {
        int o = g_off[i] + g_bpre[i / SCAN_B];
        g_off[i] = o;
        g_cursor[i] = o;
    }
    if (i == 0) g_off[NN] = NE;
}

__global__ void k_fill(const void* __restrict__ ei, const float* __restrict__ ew) {
    int e = blockIdx.x * blockDim.x + threadIdx.x;
    if (e < NE) {
        int row = load_idx(ei, e);
        int col = load_idx(ei, (long)NE + e);
        int pos = atomicAdd(&g_cursor[col], 1);
        pos = min(max(pos, 0), NE - 1);
        g_src[pos] = row;
        g_coef[pos] = g_dinv[row] * ew[e] * g_dinv[col];
    }
}

// ---------------------------------------------------------------------------
// GEMM: m[i][j] = sum_k hin[i][k] * W[j][k]   (W row-major [D][128])
// 256 threads, 64 rows/block, K chunked by 32. Static smem <= 24 KB.
// Warp owns 8 rows; lane owns cols {lane, lane+32, ...}. K vectorized by 4.
// W tile stored [col][32] with kk4 XOR-swizzle -> conflict-free LDS.128.
// ---------------------------------------------------------------------------
template <int D, bool FROM_X>
__global__ __launch_bounds__(256) void k_gemm(const float* __restrict__ x,
                                              const float* __restrict__ W) {
    const float* hin = FROM_X ? x : (const float*)g_h4;
    __shared__ alignas(16) float Ws[D * 32];
    __shared__ alignas(16) float hs[64 * 32];

    const int tid = threadIdx.x;
    const int warp = tid >> 5, lane = tid & 31;
    const int row0 = blockIdx.x * 64;
    constexpr int CPL = D / 32;  // cols per lane

    float acc[8][CPL];
#pragma unroll
    for (int r = 0; r < 8; r++)
#pragma unroll
        for (int t = 0; t < CPL; t++) acc[r][t] = 0.0f;

    for (int c = 0; c < 4; c++) {  // K chunks of 32
        for (int idx = tid; idx < D * 8; idx += 256) {
            int j = idx >> 3, kk4 = idx & 7;
            float4 v = *(const float4*)(W + j * 128 + c * 32 + kk4 * 4);
            *(float4*)(Ws + j * 32 + ((kk4 ^ (j & 7)) << 2)) = v;
        }
        for (int idx = tid; idx < 512; idx += 256) {
            int r = idx >> 3, kk4 = idx & 7;
            int gr = row0 + r;
            float4 v = (gr < NN) ? *(const float4*)(hin + (long)gr * 128 + c * 32 + kk4 * 4)
                                 : make_float4(0.f, 0.f, 0.f, 0.f);
            *(float4*)(hs + r * 32 + kk4 * 4) = v;
        }
        __syncthreads();

#pragma unroll
        for (int kk4 = 0; kk4 < 8; kk4++) {
            float4 w4[CPL];
#pragma unroll
            for (int t = 0; t < CPL; t++) {
                int col = lane + 32 * t;
                w4[t] = *(const float4*)(Ws + col * 32 + ((kk4 ^ (col & 7)) << 2));
            }
#pragma unroll
            for (int r = 0; r < 8; r++) {
                float4 h4 = *(const float4*)(hs + (warp * 8 + r) * 32 + kk4 * 4);
#pragma unroll
                for (int t = 0; t < CPL; t++) {
                    acc[r][t] += h4.x * w4[t].x;
                    acc[r][t] += h4.y * w4[t].y;
                    acc[r][t] += h4.z * w4[t].z;
                    acc[r][t] += h4.w * w4[t].w;
                }
            }
        }
        __syncthreads();
    }

    float* gm = (float*)g_m4;
#pragma unroll
    for (int r = 0; r < 8; r++) {
        int gr = row0 + warp * 8 + r;
        if (gr < NN) {
#pragma unroll
            for (int t = 0; t < CPL; t++) gm[(long)gr * D + lane + 32 * t] = acc[r][t];
        }
    }
}

// ---------------------------------------------------------------------------
// Gather-reduce per destination node, fused self-loop + bias + ReLU.
// D=128: one warp/node, lane = one float4. No atomics.
// ---------------------------------------------------------------------------
template <bool TO_OUT>
__global__ __launch_bounds__(256) void k_gather128(const float* __restrict__ b,
                                                   float* __restrict__ outp) {
    int n = (blockIdx.x * blockDim.x + threadIdx.x) >> 5;
    int lane = threadIdx.x & 31;
    if (n >= NN) return;
    int beg = g_off[n], end = g_off[n + 1];
    float dn = g_dinv[n];
    float sl = dn * dn;
    float4 acc = g_m4[n * 32 + lane];
    acc.x *= sl; acc.y *= sl; acc.z *= sl; acc.w *= sl;
#pragma unroll 4
    for (int i = beg; i < end; i++) {
        int s = g_src[i];
        float cf = g_coef[i];
        float4 v = g_m4[s * 32 + lane];
        acc.x += cf * v.x; acc.y += cf * v.y; acc.z += cf * v.z; acc.w += cf * v.w;
    }
    int j = lane * 4;  // scalar bias loads: no alignment assumption on b
    acc.x = fmaxf(acc.x + __ldg(b + j + 0), 0.0f);
    acc.y = fmaxf(acc.y + __ldg(b + j + 1), 0.0f);
    acc.z = fmaxf(acc.z + __ldg(b + j + 2), 0.0f);
    acc.w = fmaxf(acc.w + __ldg(b + j + 3), 0.0f);
    if (TO_OUT) ((float4*)outp)[n * 32 + lane] = acc;
    else        g_h4[n * 32 + lane] = acc;
}

// D=64: half-warp per node (16 float4 per row)
template <bool TO_OUT>
__global__ __launch_bounds__(256) void k_gather64(const float* __restrict__ b,
                                                  float* __restrict__ outp) {
    int gw = (blockIdx.x * blockDim.x + threadIdx.x) >> 5;
    int lane = threadIdx.x & 31;
    int n = gw * 2 + (lane >> 4);
    int l = lane & 15;
    if (n >= NN) return;
    int beg = g_off[n], end = g_off[n + 1];
    float dn = g_dinv[n];
    float sl = dn * dn;
    float4 acc = g_m4[n * 16 + l];
    acc.x *= sl; acc.y *= sl; acc.z *= sl; acc.w *= sl;
#pragma unroll 4
    for (int i = beg; i < end; i++) {
        int s = g_src[i];
        float cf = g_coef[i];
        float4 v = g_m4[s * 16 + l];
        acc.x += cf * v.x; acc.y += cf * v.y; acc.z += cf * v.z; acc.w += cf * v.w;
    }
    int j = l * 4;
    acc.x = fmaxf(acc.x + __ldg(b + j + 0), 0.0f);
    acc.y = fmaxf(acc.y + __ldg(b + j + 1), 0.0f);
    acc.z = fmaxf(acc.z + __ldg(b + j + 2), 0.0f);
    acc.w = fmaxf(acc.w + __ldg(b + j + 3), 0.0f);
    if (TO_OUT) ((float4*)outp)[n * 16 + l] = acc;
    else        g_h4[n * 16 + l] = acc;
}

// ---------------------------------------------------------------------------
extern "C" void kernel_launch(void* const* d_in, const int* in_sizes, int n_in,
                              void* d_out, int out_size) {
    const float* x = (const float*)d_in[0];
    const void*  ei = d_in[1];                 // int32 or int64 — detected on device
    const float* ew = (const float*)d_in[2];
    const float* W1 = (const float*)d_in[3];
    const float* b1 = (const float*)d_in[4];
    const float* W2 = (const float*)d_in[5];
    const float* b2 = (const float*)d_in[6];
    const float* W3 = (const float*)d_in[7];
    const float* b3 = (const float*)d_in[8];
    float* out = (float*)d_out;

    const int nB = (NN + 255) / 256;
    const int eB = (NE + 255) / 256;

    // --- dtype detect + normalization + CSR build ---
    k_detect<<<1, 256>>>((const int*)ei);
    k_zero<<<nB, 256>>>();
    k_deg_count<<<eB, 256>>>(ei, ew);
    k_dinv<<<nB, 256>>>();
    k_scan1<<<SCAN_NB, SCAN_B>>>();
    k_scan2<<<1, 32>>>();
    k_scan3<<<nB, 256>>>();
    k_fill<<<eB, 256>>>(ei, ew);

    const int gemm_blocks = (NN + 63) / 64;           // 782
    const int g128_blocks = (NN * 32 + 255) / 256;    // warp per node
    const int g64_blocks  = (NN * 16 + 255) / 256;    // half-warp per node

    // --- layer 1 (128 -> 128) ---
    k_gemm<128, true><<<gemm_blocks, 256>>>(x, W1);
    k_gather128<false><<<g128_blocks, 256>>>(b1, nullptr);

    // --- layer 2 (128 -> 128) ---
    k_gemm<128, false><<<gemm_blocks, 256>>>(nullptr, W2);
    k_gather128<false><<<g128_blocks, 256>>>(b2, nullptr);

    // --- layer 3 (128 -> 64) ---
    k_gemm<64, false><<<gemm_blocks, 256>>>(nullptr, W3);
    k_gather64<true><<<g64_blocks, 256>>>(b3, out);
}